// round 3
// baseline (speedup 1.0000x reference)
#include <cuda_runtime.h>
#include <math.h>

typedef unsigned long long ull;

// ---------------- problem constants ----------------
#define BB 128
#define TT 8
#define LL 8
#define HID 64

#define FC1_K 42240
#define FC1_N 256

// ---------------- f32x2 helpers ----------------
__device__ __forceinline__ ull pack2(float lo, float hi) {
    ull r;
    asm("mov.b64 %0, {%1, %2};" : "=l"(r) : "f"(lo), "f"(hi));
    return r;
}
__device__ __forceinline__ ull dup2(float v) {
    ull r;
    asm("mov.b64 %0, {%1, %1};" : "=l"(r) : "f"(v));
    return r;
}
__device__ __forceinline__ void unpack2(ull v, float& lo, float& hi) {
    asm("mov.b64 {%0, %1}, %2;" : "=f"(lo), "=f"(hi) : "l"(v));
}
__device__ __forceinline__ void fma2(ull& acc, ull a, ull b) {
    asm("fma.rn.f32x2 %0, %1, %2, %0;" : "+l"(acc) : "l"(a), "l"(b));
}

// ---------------- scratch ----------------
__device__ float g_c1[(size_t)BB * 32 * 94 * 126];
__device__ float g_c2[(size_t)BB * 64 * 46 * 62];
__device__ float g_c3[(size_t)BB * 64 * 22 * 30];
__device__ float g_fc1[BB * FC1_N];
__device__ float g_cnn1[BB * 128];
__device__ float g_cnn2[BB * 128];
__device__ float g_act1[BB * TT * 16];
__device__ float g_a[BB * TT * 16];
__device__ float g_h[LL * TT * BB * HID];
__device__ float g_cst[LL * TT * BB * HID];
__device__ float g_lstm_out[BB * TT * HID];
__device__ float g_out1[BB * TT * 32];
__device__ float g_mo[BB * TT * 4];

// ---------------- conv: compile-time dims, smem weights, f32x2 FMA ----------------
template <int CIN, int KS, int HI, int WI, int HO, int WO, int CO, bool RELU>
__global__ void conv_s2_f2(const float* __restrict__ in,
                           const float* __restrict__ wt,
                           const float* __restrict__ bs,
                           float* __restrict__ out)
{
    constexpr int WSZ = CIN * KS * KS * 4;
    __shared__ float Wsm[WSZ];
    __shared__ float Bsm[4];

    const int co0 = blockIdx.y * 4;
    const int n   = blockIdx.z;
    constexpr int wstride = CIN * KS * KS;

    for (int idx = threadIdx.x; idx < WSZ; idx += blockDim.x) {
        int c = idx & 3;
        int ckk = idx >> 2;
        Wsm[idx] = wt[(co0 + c) * wstride + ckk];
    }
    if (threadIdx.x < 4) Bsm[threadIdx.x] = bs[co0 + threadIdx.x];
    __syncthreads();

    constexpr int WO4 = (WO + 3) >> 2;
    int pix = blockIdx.x * blockDim.x + threadIdx.x;
    if (pix >= HO * WO4) return;
    int ho  = pix / WO4;
    int wo0 = (pix % WO4) * 4;

    // accp[p][j]: pair of channels (2p, 2p+1) for output col j
    ull accp[2][4];
    {
        ull b01 = pack2(Bsm[0], Bsm[1]);
        ull b23 = pack2(Bsm[2], Bsm[3]);
        #pragma unroll
        for (int j = 0; j < 4; j++) { accp[0][j] = b01; accp[1][j] = b23; }
    }

    constexpr int WIN = KS + 6;
    constexpr int NV2 = (WIN + 1) / 2;
    const bool fast = (wo0 + 4 <= WO);

    const float* ibase = in + ((long)n * CIN) * (HI * WI) + (ho * 2) * WI + wo0 * 2;

    #pragma unroll 1
    for (int ci = 0; ci < CIN; ci++) {
        #pragma unroll
        for (int kh = 0; kh < KS; kh++) {
            const float* irow = ibase + ci * (HI * WI) + kh * WI;
            ull pv[NV2 * 2];
            if (fast) {
                const float2* p = reinterpret_cast<const float2*>(irow);
                #pragma unroll
                for (int v = 0; v < NV2; v++) {
                    float2 t2 = p[v];
                    pv[2 * v]     = dup2(t2.x);
                    pv[2 * v + 1] = dup2(t2.y);
                }
            } else {
                #pragma unroll
                for (int v = 0; v < NV2 * 2; v++) {
                    int col = wo0 * 2 + v;
                    pv[v] = dup2((col < WI) ? irow[v] : 0.0f);
                }
            }
            #pragma unroll
            for (int kw = 0; kw < KS; kw++) {
                float4 wv = *reinterpret_cast<const float4*>(&Wsm[(ci * KS * KS + kh * KS + kw) * 4]);
                ull w01 = pack2(wv.x, wv.y);
                ull w23 = pack2(wv.z, wv.w);
                #pragma unroll
                for (int j = 0; j < 4; j++) {
                    fma2(accp[0][j], w01, pv[2 * j + kw]);
                    fma2(accp[1][j], w23, pv[2 * j + kw]);
                }
            }
        }
    }

    float* obase = out + ((long)(n * CO + co0)) * (HO * WO) + ho * WO + wo0;
    #pragma unroll
    for (int p = 0; p < 2; p++) {
        #pragma unroll
        for (int j = 0; j < 4; j++) {
            float v0, v1;
            unpack2(accp[p][j], v0, v1);
            if (RELU) { v0 = fmaxf(v0, 0.0f); v1 = fmaxf(v1, 0.0f); }
            if (wo0 + j < WO) {
                obase[(2 * p)     * (HO * WO) + j] = v0;
                obase[(2 * p + 1) * (HO * WO) + j] = v1;
            }
        }
    }
}

// ---------------- fc1 ----------------
__global__ void fc1_init_kernel(const float* __restrict__ b, float* __restrict__ C)
{
    int idx = blockIdx.x * blockDim.x + threadIdx.x;
    if (idx < BB * FC1_N) C[idx] = b[idx % FC1_N];
}

__global__ void fc1_gemm_kernel(const float* __restrict__ A,
                                const float* __restrict__ B,
                                float* __restrict__ C)
{
    __shared__ float As[16][72];
    __shared__ float Bs[16][72];

    const int tid = threadIdx.x;
    const int m0 = blockIdx.y * 64;
    const int n0 = blockIdx.x * 64;
    const int k0 = blockIdx.z * 1280;

    const int lr = tid >> 2;
    const int lc = (tid & 3) * 4;

    const float* Ap = A + (long)(m0 + lr) * FC1_K + k0 + lc;
    const float* Bp = B + (long)(n0 + lr) * FC1_K + k0 + lc;

    const int ty = tid >> 4, tx = tid & 15;
    // acc pairs over n: accp[i][0]=(n0,n1), accp[i][1]=(n2,n3)
    ull accp[4][2];
    #pragma unroll
    for (int i = 0; i < 4; i++) { accp[i][0] = 0ull; accp[i][1] = 0ull; }

    for (int it = 0; it < 80; it++) {
        float4 av = *reinterpret_cast<const float4*>(Ap + it * 16);
        float4 bv = *reinterpret_cast<const float4*>(Bp + it * 16);
        __syncthreads();
        As[lc + 0][lr] = av.x; As[lc + 1][lr] = av.y; As[lc + 2][lr] = av.z; As[lc + 3][lr] = av.w;
        Bs[lc + 0][lr] = bv.x; Bs[lc + 1][lr] = bv.y; Bs[lc + 2][lr] = bv.z; Bs[lc + 3][lr] = bv.w;
        __syncthreads();
        #pragma unroll
        for (int kk = 0; kk < 16; kk++) {
            float4 a4 = *reinterpret_cast<const float4*>(&As[kk][ty * 4]);
            float4 b4 = *reinterpret_cast<const float4*>(&Bs[kk][tx * 4]);
            ull b01 = pack2(b4.x, b4.y);
            ull b23 = pack2(b4.z, b4.w);
            float a[4] = {a4.x, a4.y, a4.z, a4.w};
            #pragma unroll
            for (int i = 0; i < 4; i++) {
                ull a2 = dup2(a[i]);
                fma2(accp[i][0], a2, b01);
                fma2(accp[i][1], a2, b23);
            }
        }
    }

    #pragma unroll
    for (int i = 0; i < 4; i++) {
        #pragma unroll
        for (int p = 0; p < 2; p++) {
            float v0, v1;
            unpack2(accp[i][p], v0, v1);
            atomicAdd(&C[(m0 + ty * 4 + i) * FC1_N + (n0 + tx * 4 + 2 * p)],     v0);
            atomicAdd(&C[(m0 + ty * 4 + i) * FC1_N + (n0 + tx * 4 + 2 * p + 1)], v1);
        }
    }
}

// ---------------- small linear ----------------
__global__ void lin2_kernel(const float* __restrict__ in,
                            const float* __restrict__ w,
                            const float* __restrict__ bias,
                            float* __restrict__ out,
                            int M, int N, int K, int reluIn)
{
    __shared__ float Xs[256 * 33];

    const int tid = threadIdx.x;
    const int m0 = blockIdx.x * 32;
    const int n0 = blockIdx.y * 32;

    for (int idx = tid; idx < 32 * K; idx += 256) {
        int m_l = idx / K;
        int k = idx - m_l * K;
        float v = in[(long)(m0 + m_l) * K + k];
        if (reluIn) v = fmaxf(v, 0.0f);
        Xs[k * 33 + m_l] = v;
    }
    __syncthreads();

    const int lane = tid & 31;
    const int wg = tid >> 5;
    const int m = m0 + lane;

    float acc[4] = {0.f, 0.f, 0.f, 0.f};
    const int K4 = K & ~3;

    for (int k4 = 0; k4 < K4; k4 += 4) {
        float xv0 = Xs[(k4 + 0) * 33 + lane];
        float xv1 = Xs[(k4 + 1) * 33 + lane];
        float xv2 = Xs[(k4 + 2) * 33 + lane];
        float xv3 = Xs[(k4 + 3) * 33 + lane];
        #pragma unroll
        for (int ni = 0; ni < 4; ni++) {
            int nn = n0 + wg * 4 + ni;
            if (nn < N) {
                float4 wv = *reinterpret_cast<const float4*>(&w[(long)nn * K + k4]);
                acc[ni] += xv0 * wv.x + xv1 * wv.y + xv2 * wv.z + xv3 * wv.w;
            }
        }
    }
    for (int k = K4; k < K; k++) {
        float xv = Xs[k * 33 + lane];
        #pragma unroll
        for (int ni = 0; ni < 4; ni++) {
            int nn = n0 + wg * 4 + ni;
            if (nn < N) acc[ni] += xv * w[(long)nn * K + k];
        }
    }

    #pragma unroll
    for (int ni = 0; ni < 4; ni++) {
        int nn = n0 + wg * 4 + ni;
        if (nn < N) out[(long)m * N + nn] = acc[ni] + bias[nn];
    }
}

// ---------------- LSTM wave kernel ----------------
__device__ __forceinline__ float sigf(float x) { return 1.0f / (1.0f + expf(-x)); }

__global__ void lstm_wave2_kernel(int wave,
                                  const float* __restrict__ a,
                                  const float* __restrict__ cnn2,
                                  const float* __restrict__ Wih0,
                                  const float* __restrict__ Wih,
                                  const float* __restrict__ Whh,
                                  const float* __restrict__ bih,
                                  const float* __restrict__ bhh,
                                  float* __restrict__ h_arr,
                                  float* __restrict__ c_arr,
                                  float* __restrict__ lstm_out)
{
    __shared__ float Ws[32 * 257];
    __shared__ float Xs[32 * 9];

    const int cell = blockIdx.x >> 4;
    const int bblk = blockIdx.x & 15;
    int l_lo = wave - (TT - 1); if (l_lo < 0) l_lo = 0;
    const int l = l_lo + cell;
    const int t = wave - l;

    const int tid = threadIdx.x;
    const int j = tid & 63;
    const int bq = tid >> 6;
    const int b0 = bblk * 8;

    float acc[4][2];
    #pragma unroll
    for (int q = 0; q < 4; q++) {
        float bb = bih[l * 256 + q * 64 + j] + bhh[l * 256 + q * 64 + j];
        acc[q][0] = bb; acc[q][1] = bb;
    }

    #pragma unroll 1
    for (int ph = 0; ph < 2; ph++) {
        const float* W;
        const float* xbase;
        int K, xstr;
        if (ph == 0) {
            if (l == 0) { W = Wih0; K = 16; xbase = a + t * 16; xstr = TT * 16; }
            else        { W = Wih + (long)(l - 1) * 256 * 64; K = 64;
                          xbase = h_arr + ((long)((l - 1) * TT + t)) * BB * 64; xstr = 64; }
        } else {
            W = Whh + (long)l * 256 * 64; K = 64;
            if (t == 0) { xbase = cnn2 + HID; xstr = 128; }
            else        { xbase = h_arr + ((long)(l * TT + (t - 1))) * BB * 64; xstr = 64; }
        }

        for (int k0 = 0; k0 < K; k0 += 32) {
            int kc = (K - k0 < 32) ? (K - k0) : 32;
            __syncthreads();
            for (int idx = tid; idx < kc * 256; idx += 256) {
                int r = idx / kc;
                int k = idx - r * kc;
                Ws[k * 257 + r] = W[(long)r * K + k0 + k];
            }
            for (int idx = tid; idx < kc * 8; idx += 256) {
                int b_l = idx / kc;
                int k = idx - b_l * kc;
                Xs[k * 9 + b_l] = xbase[(long)(b0 + b_l) * xstr + k0 + k];
            }
            __syncthreads();
            #pragma unroll 8
            for (int k = 0; k < kc; k++) {
                float xv0 = Xs[k * 9 + (bq << 1)];
                float xv1 = Xs[k * 9 + (bq << 1) + 1];
                float w0 = Ws[k * 257 + j];
                float w1 = Ws[k * 257 + 64 + j];
                float w2 = Ws[k * 257 + 128 + j];
                float w3 = Ws[k * 257 + 192 + j];
                acc[0][0] += w0 * xv0; acc[0][1] += w0 * xv1;
                acc[1][0] += w1 * xv0; acc[1][1] += w1 * xv1;
                acc[2][0] += w2 * xv0; acc[2][1] += w2 * xv1;
                acc[3][0] += w3 * xv0; acc[3][1] += w3 * xv1;
            }
        }
    }

    #pragma unroll
    for (int i = 0; i < 2; i++) {
        int b = b0 + (bq << 1) + i;
        float c_prev = (t == 0) ? cnn2[b * 128 + j]
                                : c_arr[((long)(l * TT + (t - 1)) * BB + b) * 64 + j];
        float i_ = sigf(acc[0][i]);
        float f_ = sigf(acc[1][i]);
        float gg = tanhf(acc[2][i]);
        float o_ = sigf(acc[3][i]);
        float c  = f_ * c_prev + i_ * gg;
        float h  = o_ * tanhf(c);
        long pos = ((long)(l * TT + t) * BB + b) * 64 + j;
        h_arr[pos] = h;
        c_arr[pos] = c;
        if (l == LL - 1) lstm_out[(b * TT + t) * 64 + j] = h;
    }
}

// ---------------- finalize ----------------
__global__ void finalize_kernel(const float* __restrict__ mo,
                                const float* __restrict__ gt,
                                float* __restrict__ out)
{
    int idx = blockIdx.x * blockDim.x + threadIdx.x;
    if (idx >= BB * TT) return;
    int b = idx / TT;
    float yaw = gt[b * (TT * 6) + 5];
    float cy = cosf(yaw), sy = sinf(yaw);
    float m0 = mo[idx * 4 + 0];
    float m1 = mo[idx * 4 + 1];
    float m2 = mo[idx * 4 + 2];
    float m3 = mo[idx * 4 + 3];
    float tx = gt[b * (TT * 6) + 1];
    float ty = gt[b * (TT * 6) + 2];
    float tz = gt[b * (TT * 6) + 3];
    out[idx * 4 + 0] =  m0 * cy + m1 * sy + tx;
    out[idx * 4 + 1] = -m0 * sy + m1 * cy + ty;
    out[idx * 4 + 2] =  m2 + tz;
    out[idx * 4 + 3] =  m3;
}

// ---------------- launch ----------------
extern "C" void kernel_launch(void* const* d_in, const int* in_sizes, int n_in,
                              void* d_out, int out_size)
{
    const float* image    = (const float*)d_in[0];
    const float* act_in   = (const float*)d_in[1];
    const float* gt       = (const float*)d_in[2];
    const float* conv1_w  = (const float*)d_in[3];
    const float* conv1_b  = (const float*)d_in[4];
    const float* conv2_w  = (const float*)d_in[5];
    const float* conv2_b  = (const float*)d_in[6];
    const float* conv3_w  = (const float*)d_in[7];
    const float* conv3_b  = (const float*)d_in[8];
    const float* fc1_w    = (const float*)d_in[9];
    const float* fc1_b    = (const float*)d_in[10];
    const float* fc2_w    = (const float*)d_in[11];
    const float* fc2_b    = (const float*)d_in[12];
    const float* lowd1_w  = (const float*)d_in[13];
    const float* lowd1_b  = (const float*)d_in[14];
    const float* lowd2_w  = (const float*)d_in[15];
    const float* lowd2_b  = (const float*)d_in[16];
    const float* act1_w   = (const float*)d_in[17];
    const float* act1_b   = (const float*)d_in[18];
    const float* act2_w   = (const float*)d_in[19];
    const float* act2_b   = (const float*)d_in[20];
    const float* Wih0     = (const float*)d_in[21];
    const float* Wih      = (const float*)d_in[22];
    const float* Whh      = (const float*)d_in[23];
    const float* bih      = (const float*)d_in[24];
    const float* bhh      = (const float*)d_in[25];
    const float* out1_w   = (const float*)d_in[26];
    const float* out1_b   = (const float*)d_in[27];
    const float* out2_w   = (const float*)d_in[28];
    const float* out2_b   = (const float*)d_in[29];
    float* out = (float*)d_out;

    float *c1, *c2, *c3, *fc1o, *cnn1, *cnn2, *a1, *a2, *hA, *cA, *lo, *o1, *mo;
    cudaGetSymbolAddress((void**)&c1,   g_c1);
    cudaGetSymbolAddress((void**)&c2,   g_c2);
    cudaGetSymbolAddress((void**)&c3,   g_c3);
    cudaGetSymbolAddress((void**)&fc1o, g_fc1);
    cudaGetSymbolAddress((void**)&cnn1, g_cnn1);
    cudaGetSymbolAddress((void**)&cnn2, g_cnn2);
    cudaGetSymbolAddress((void**)&a1,   g_act1);
    cudaGetSymbolAddress((void**)&a2,   g_a);
    cudaGetSymbolAddress((void**)&hA,   g_h);
    cudaGetSymbolAddress((void**)&cA,   g_cst);
    cudaGetSymbolAddress((void**)&lo,   g_lstm_out);
    cudaGetSymbolAddress((void**)&o1,   g_out1);
    cudaGetSymbolAddress((void**)&mo,   g_mo);

    // conv1: Ho*WO4 = 94*32 = 3008
    {
        dim3 grid((3008 + 255) / 256, 32 / 4, BB);
        conv_s2_f2<3, 5, 192, 256, 94, 126, 32, true><<<grid, 256>>>(image, conv1_w, conv1_b, c1);
    }
    // conv2: 46*16 = 736
    {
        dim3 grid((736 + 255) / 256, 64 / 4, BB);
        conv_s2_f2<32, 3, 94, 126, 46, 62, 64, true><<<grid, 256>>>(c1, conv2_w, conv2_b, c2);
    }
    // conv3: 22*8 = 176
    {
        dim3 grid(1, 64 / 4, BB);
        conv_s2_f2<64, 3, 46, 62, 22, 30, 64, false><<<grid, 192>>>(c2, conv3_w, conv3_b, c3);
    }
    // fc1
    fc1_init_kernel<<<(BB * FC1_N + 255) / 256, 256>>>(fc1_b, fc1o);
    {
        dim3 grid(FC1_N / 64, BB / 64, 33);
        fc1_gemm_kernel<<<grid, 256>>>(c3, fc1_w, fc1o);
    }
    // fc2 / lowd chain
    { dim3 g(BB / 32, 4); lin2_kernel<<<g, 256>>>(fc1o, fc2_w, fc2_b, cnn1, BB, 128, 256, 1); }
    { dim3 g(BB / 32, 4); lin2_kernel<<<g, 256>>>(cnn1, lowd1_w, lowd1_b, cnn2, BB, 128, 128, 0); }
    { dim3 g(BB / 32, 4); lin2_kernel<<<g, 256>>>(cnn2, lowd2_w, lowd2_b, cnn1, BB, 128, 128, 1); }
    // action path
    { dim3 g(BB * TT / 32, 1); lin2_kernel<<<g, 256>>>(act_in, act1_w, act1_b, a1, BB * TT, 16, 2, 0); }
    { dim3 g(BB * TT / 32, 1); lin2_kernel<<<g, 256>>>(a1, act2_w, act2_b, a2, BB * TT, 16, 16, 1); }

    // LSTM: 15 waves
    for (int w = 0; w < LL + TT - 1; w++) {
        int l_lo = w - (TT - 1); if (l_lo < 0) l_lo = 0;
        int l_hi = w; if (l_hi > LL - 1) l_hi = LL - 1;
        int ncells = l_hi - l_lo + 1;
        lstm_wave2_kernel<<<ncells * 16, 256>>>(w, a2, cnn1, Wih0, Wih, Whh, bih, bhh, hA, cA, lo);
    }

    // heads
    { dim3 g(BB * TT / 32, 1); lin2_kernel<<<g, 256>>>(lo, out1_w, out1_b, o1, BB * TT, 32, 64, 0); }
    { dim3 g(BB * TT / 32, 1); lin2_kernel<<<g, 256>>>(o1, out2_w, out2_b, mo, BB * TT, 4, 32, 1); }

    finalize_kernel<<<(BB * TT + 255) / 256, 256>>>(mo, gt, out);
}

// round 4
// speedup vs baseline: 1.3710x; 1.3710x over previous
#include <cuda_runtime.h>
#include <math.h>

// ---------------- problem constants ----------------
#define BB 128
#define TT 8
#define LL 8
#define HID 64

#define FC1_K 42240
#define FC1_N 256

// ---------------- scratch ----------------
__device__ float g_c1[(size_t)BB * 32 * 94 * 126];
__device__ float g_c2[(size_t)BB * 64 * 46 * 62];
__device__ float g_c3[(size_t)BB * 64 * 22 * 30];
__device__ float g_fc1[BB * FC1_N];
__device__ float g_cnn1[BB * 128];
__device__ float g_cnn2[BB * 128];
__device__ float g_act1[BB * TT * 16];
__device__ float g_a[BB * TT * 16];
__device__ float g_h[LL * TT * BB * HID];
__device__ float g_cst[LL * TT * BB * HID];
__device__ float g_lstm_out[BB * TT * HID];
__device__ float g_out1[BB * TT * 32];
__device__ float g_mo[BB * TT * 4];

// ---------------- conv: compile-time dims, smem weights, 8co x 4wo microtile ----------------
template <int CIN, int KS, int HI, int WI, int HO, int WO, int CO, bool RELU>
__global__ void conv_s2_c8(const float* __restrict__ in,
                           const float* __restrict__ wt,
                           const float* __restrict__ bs,
                           float* __restrict__ out)
{
    constexpr int NTAP = CIN * KS * KS;
    constexpr int WSZ = NTAP * 8;
    __shared__ float Wsm[WSZ];
    __shared__ float Bsm[8];

    const int co0 = blockIdx.y * 8;
    const int n   = blockIdx.z;

    // stage weights transposed: Wsm[tap*8 + c] = wt[(co0+c)*NTAP + tap]
    for (int idx = threadIdx.x; idx < WSZ; idx += blockDim.x) {
        int c = idx & 7;
        int tap = idx >> 3;
        Wsm[idx] = wt[(co0 + c) * NTAP + tap];
    }
    if (threadIdx.x < 8) Bsm[threadIdx.x] = bs[co0 + threadIdx.x];
    __syncthreads();

    constexpr int WO4 = (WO + 3) >> 2;
    int pix = blockIdx.x * blockDim.x + threadIdx.x;
    if (pix >= HO * WO4) return;
    int ho  = pix / WO4;
    int wo0 = (pix % WO4) * 4;

    float acc[8][4];
    #pragma unroll
    for (int c = 0; c < 8; c++) {
        float bv = Bsm[c];
        #pragma unroll
        for (int j = 0; j < 4; j++) acc[c][j] = bv;
    }

    constexpr int WIN = KS + 6;
    constexpr int NV2 = (WIN + 1) / 2;
    const bool fast = (wo0 + 4 <= WO);

    const float* ibase = in + ((long)n * CIN) * (HI * WI) + (ho * 2) * WI + wo0 * 2;

    #pragma unroll 1
    for (int ci = 0; ci < CIN; ci++) {
        #pragma unroll
        for (int kh = 0; kh < KS; kh++) {
            const float* irow = ibase + ci * (HI * WI) + kh * WI;
            float vals[NV2 * 2];
            if (fast) {
                const float2* p = reinterpret_cast<const float2*>(irow);
                #pragma unroll
                for (int v = 0; v < NV2; v++) {
                    float2 t2 = p[v];
                    vals[2 * v] = t2.x; vals[2 * v + 1] = t2.y;
                }
            } else {
                #pragma unroll
                for (int v = 0; v < NV2 * 2; v++) {
                    int col = wo0 * 2 + v;
                    vals[v] = (col < WI) ? irow[v] : 0.0f;
                }
            }
            #pragma unroll
            for (int kw = 0; kw < KS; kw++) {
                const float* wp = &Wsm[(ci * KS * KS + kh * KS + kw) * 8];
                float4 wa = *reinterpret_cast<const float4*>(wp);
                float4 wb = *reinterpret_cast<const float4*>(wp + 4);
                #pragma unroll
                for (int j = 0; j < 4; j++) {
                    float iv = vals[2 * j + kw];
                    acc[0][j] += iv * wa.x;
                    acc[1][j] += iv * wa.y;
                    acc[2][j] += iv * wa.z;
                    acc[3][j] += iv * wa.w;
                    acc[4][j] += iv * wb.x;
                    acc[5][j] += iv * wb.y;
                    acc[6][j] += iv * wb.z;
                    acc[7][j] += iv * wb.w;
                }
            }
        }
    }

    float* obase = out + ((long)(n * CO + co0)) * (HO * WO) + ho * WO + wo0;
    #pragma unroll
    for (int c = 0; c < 8; c++) {
        #pragma unroll
        for (int j = 0; j < 4; j++) {
            if (wo0 + j < WO) {
                float v = acc[c][j];
                if (RELU) v = fmaxf(v, 0.0f);
                obase[c * (HO * WO) + j] = v;
            }
        }
    }
}

// ---------------- fc1 ----------------
__global__ void fc1_init_kernel(const float* __restrict__ b, float* __restrict__ C)
{
    int idx = blockIdx.x * blockDim.x + threadIdx.x;
    if (idx < BB * FC1_N) C[idx] = b[idx % FC1_N];
}

__global__ void fc1_gemm_kernel(const float* __restrict__ A,
                                const float* __restrict__ B,
                                float* __restrict__ C)
{
    __shared__ float As[16][72];
    __shared__ float Bs[16][72];

    const int tid = threadIdx.x;
    const int m0 = blockIdx.y * 64;
    const int n0 = blockIdx.x * 64;
    const int k0 = blockIdx.z * 1280;

    const int lr = tid >> 2;
    const int lc = (tid & 3) * 4;

    const float* Ap = A + (long)(m0 + lr) * FC1_K + k0 + lc;
    const float* Bp = B + (long)(n0 + lr) * FC1_K + k0 + lc;

    const int ty = tid >> 4, tx = tid & 15;
    float acc[4][4] = {};

    for (int it = 0; it < 80; it++) {
        float4 av = *reinterpret_cast<const float4*>(Ap + it * 16);
        float4 bv = *reinterpret_cast<const float4*>(Bp + it * 16);
        __syncthreads();
        As[lc + 0][lr] = av.x; As[lc + 1][lr] = av.y; As[lc + 2][lr] = av.z; As[lc + 3][lr] = av.w;
        Bs[lc + 0][lr] = bv.x; Bs[lc + 1][lr] = bv.y; Bs[lc + 2][lr] = bv.z; Bs[lc + 3][lr] = bv.w;
        __syncthreads();
        #pragma unroll
        for (int kk = 0; kk < 16; kk++) {
            float4 a4 = *reinterpret_cast<const float4*>(&As[kk][ty * 4]);
            float4 b4 = *reinterpret_cast<const float4*>(&Bs[kk][tx * 4]);
            float a[4] = {a4.x, a4.y, a4.z, a4.w};
            float b[4] = {b4.x, b4.y, b4.z, b4.w};
            #pragma unroll
            for (int i = 0; i < 4; i++)
                #pragma unroll
                for (int j = 0; j < 4; j++)
                    acc[i][j] += a[i] * b[j];
        }
    }

    #pragma unroll
    for (int i = 0; i < 4; i++)
        #pragma unroll
        for (int j = 0; j < 4; j++)
            atomicAdd(&C[(m0 + ty * 4 + i) * FC1_N + (n0 + tx * 4 + j)], acc[i][j]);
}

// ---------------- small linear ----------------
__global__ void lin2_kernel(const float* __restrict__ in,
                            const float* __restrict__ w,
                            const float* __restrict__ bias,
                            float* __restrict__ out,
                            int M, int N, int K, int reluIn)
{
    __shared__ float Xs[256 * 33];

    const int tid = threadIdx.x;
    const int m0 = blockIdx.x * 32;
    const int n0 = blockIdx.y * 32;

    for (int idx = tid; idx < 32 * K; idx += 256) {
        int m_l = idx / K;
        int k = idx - m_l * K;
        float v = in[(long)(m0 + m_l) * K + k];
        if (reluIn) v = fmaxf(v, 0.0f);
        Xs[k * 33 + m_l] = v;
    }
    __syncthreads();

    const int lane = tid & 31;
    const int wg = tid >> 5;
    const int m = m0 + lane;

    float acc[4] = {0.f, 0.f, 0.f, 0.f};
    const int K4 = K & ~3;

    for (int k4 = 0; k4 < K4; k4 += 4) {
        float xv0 = Xs[(k4 + 0) * 33 + lane];
        float xv1 = Xs[(k4 + 1) * 33 + lane];
        float xv2 = Xs[(k4 + 2) * 33 + lane];
        float xv3 = Xs[(k4 + 3) * 33 + lane];
        #pragma unroll
        for (int ni = 0; ni < 4; ni++) {
            int nn = n0 + wg * 4 + ni;
            if (nn < N) {
                float4 wv = *reinterpret_cast<const float4*>(&w[(long)nn * K + k4]);
                acc[ni] += xv0 * wv.x + xv1 * wv.y + xv2 * wv.z + xv3 * wv.w;
            }
        }
    }
    for (int k = K4; k < K; k++) {
        float xv = Xs[k * 33 + lane];
        #pragma unroll
        for (int ni = 0; ni < 4; ni++) {
            int nn = n0 + wg * 4 + ni;
            if (nn < N) acc[ni] += xv * w[(long)nn * K + k];
        }
    }

    #pragma unroll
    for (int ni = 0; ni < 4; ni++) {
        int nn = n0 + wg * 4 + ni;
        if (nn < N) out[(long)m * N + nn] = acc[ni] + bias[nn];
    }
}

// ---------------- LSTM wave kernel ----------------
__device__ __forceinline__ float sigf(float x) { return 1.0f / (1.0f + expf(-x)); }

__global__ void lstm_wave2_kernel(int wave,
                                  const float* __restrict__ a,
                                  const float* __restrict__ cnn2,
                                  const float* __restrict__ Wih0,
                                  const float* __restrict__ Wih,
                                  const float* __restrict__ Whh,
                                  const float* __restrict__ bih,
                                  const float* __restrict__ bhh,
                                  float* __restrict__ h_arr,
                                  float* __restrict__ c_arr,
                                  float* __restrict__ lstm_out)
{
    __shared__ float Ws[32 * 257];
    __shared__ float Xs[32 * 9];

    const int cell = blockIdx.x >> 4;
    const int bblk = blockIdx.x & 15;
    int l_lo = wave - (TT - 1); if (l_lo < 0) l_lo = 0;
    const int l = l_lo + cell;
    const int t = wave - l;

    const int tid = threadIdx.x;
    const int j = tid & 63;
    const int bq = tid >> 6;
    const int b0 = bblk * 8;

    float acc[4][2];
    #pragma unroll
    for (int q = 0; q < 4; q++) {
        float bb = bih[l * 256 + q * 64 + j] + bhh[l * 256 + q * 64 + j];
        acc[q][0] = bb; acc[q][1] = bb;
    }

    #pragma unroll 1
    for (int ph = 0; ph < 2; ph++) {
        const float* W;
        const float* xbase;
        int K, xstr;
        if (ph == 0) {
            if (l == 0) { W = Wih0; K = 16; xbase = a + t * 16; xstr = TT * 16; }
            else        { W = Wih + (long)(l - 1) * 256 * 64; K = 64;
                          xbase = h_arr + ((long)((l - 1) * TT + t)) * BB * 64; xstr = 64; }
        } else {
            W = Whh + (long)l * 256 * 64; K = 64;
            if (t == 0) { xbase = cnn2 + HID; xstr = 128; }
            else        { xbase = h_arr + ((long)(l * TT + (t - 1))) * BB * 64; xstr = 64; }
        }

        for (int k0 = 0; k0 < K; k0 += 32) {
            int kc = (K - k0 < 32) ? (K - k0) : 32;
            __syncthreads();
            for (int idx = tid; idx < kc * 256; idx += 256) {
                int r = idx / kc;
                int k = idx - r * kc;
                Ws[k * 257 + r] = W[(long)r * K + k0 + k];
            }
            for (int idx = tid; idx < kc * 8; idx += 256) {
                int b_l = idx / kc;
                int k = idx - b_l * kc;
                Xs[k * 9 + b_l] = xbase[(long)(b0 + b_l) * xstr + k0 + k];
            }
            __syncthreads();
            #pragma unroll 8
            for (int k = 0; k < kc; k++) {
                float xv0 = Xs[k * 9 + (bq << 1)];
                float xv1 = Xs[k * 9 + (bq << 1) + 1];
                float w0 = Ws[k * 257 + j];
                float w1 = Ws[k * 257 + 64 + j];
                float w2 = Ws[k * 257 + 128 + j];
                float w3 = Ws[k * 257 + 192 + j];
                acc[0][0] += w0 * xv0; acc[0][1] += w0 * xv1;
                acc[1][0] += w1 * xv0; acc[1][1] += w1 * xv1;
                acc[2][0] += w2 * xv0; acc[2][1] += w2 * xv1;
                acc[3][0] += w3 * xv0; acc[3][1] += w3 * xv1;
            }
        }
    }

    #pragma unroll
    for (int i = 0; i < 2; i++) {
        int b = b0 + (bq << 1) + i;
        float c_prev = (t == 0) ? cnn2[b * 128 + j]
                                : c_arr[((long)(l * TT + (t - 1)) * BB + b) * 64 + j];
        float i_ = sigf(acc[0][i]);
        float f_ = sigf(acc[1][i]);
        float gg = tanhf(acc[2][i]);
        float o_ = sigf(acc[3][i]);
        float c  = f_ * c_prev + i_ * gg;
        float h  = o_ * tanhf(c);
        long pos = ((long)(l * TT + t) * BB + b) * 64 + j;
        h_arr[pos] = h;
        c_arr[pos] = c;
        if (l == LL - 1) lstm_out[(b * TT + t) * 64 + j] = h;
    }
}

// ---------------- finalize ----------------
__global__ void finalize_kernel(const float* __restrict__ mo,
                                const float* __restrict__ gt,
                                float* __restrict__ out)
{
    int idx = blockIdx.x * blockDim.x + threadIdx.x;
    if (idx >= BB * TT) return;
    int b = idx / TT;
    float yaw = gt[b * (TT * 6) + 5];
    float cy = cosf(yaw), sy = sinf(yaw);
    float m0 = mo[idx * 4 + 0];
    float m1 = mo[idx * 4 + 1];
    float m2 = mo[idx * 4 + 2];
    float m3 = mo[idx * 4 + 3];
    float tx = gt[b * (TT * 6) + 1];
    float ty = gt[b * (TT * 6) + 2];
    float tz = gt[b * (TT * 6) + 3];
    out[idx * 4 + 0] =  m0 * cy + m1 * sy + tx;
    out[idx * 4 + 1] = -m0 * sy + m1 * cy + ty;
    out[idx * 4 + 2] =  m2 + tz;
    out[idx * 4 + 3] =  m3;
}

// ---------------- launch ----------------
extern "C" void kernel_launch(void* const* d_in, const int* in_sizes, int n_in,
                              void* d_out, int out_size)
{
    const float* image    = (const float*)d_in[0];
    const float* act_in   = (const float*)d_in[1];
    const float* gt       = (const float*)d_in[2];
    const float* conv1_w  = (const float*)d_in[3];
    const float* conv1_b  = (const float*)d_in[4];
    const float* conv2_w  = (const float*)d_in[5];
    const float* conv2_b  = (const float*)d_in[6];
    const float* conv3_w  = (const float*)d_in[7];
    const float* conv3_b  = (const float*)d_in[8];
    const float* fc1_w    = (const float*)d_in[9];
    const float* fc1_b    = (const float*)d_in[10];
    const float* fc2_w    = (const float*)d_in[11];
    const float* fc2_b    = (const float*)d_in[12];
    const float* lowd1_w  = (const float*)d_in[13];
    const float* lowd1_b  = (const float*)d_in[14];
    const float* lowd2_w  = (const float*)d_in[15];
    const float* lowd2_b  = (const float*)d_in[16];
    const float* act1_w   = (const float*)d_in[17];
    const float* act1_b   = (const float*)d_in[18];
    const float* act2_w   = (const float*)d_in[19];
    const float* act2_b   = (const float*)d_in[20];
    const float* Wih0     = (const float*)d_in[21];
    const float* Wih      = (const float*)d_in[22];
    const float* Whh      = (const float*)d_in[23];
    const float* bih      = (const float*)d_in[24];
    const float* bhh      = (const float*)d_in[25];
    const float* out1_w   = (const float*)d_in[26];
    const float* out1_b   = (const float*)d_in[27];
    const float* out2_w   = (const float*)d_in[28];
    const float* out2_b   = (const float*)d_in[29];
    float* out = (float*)d_out;

    float *c1, *c2, *c3, *fc1o, *cnn1, *cnn2, *a1, *a2, *hA, *cA, *lo, *o1, *mo;
    cudaGetSymbolAddress((void**)&c1,   g_c1);
    cudaGetSymbolAddress((void**)&c2,   g_c2);
    cudaGetSymbolAddress((void**)&c3,   g_c3);
    cudaGetSymbolAddress((void**)&fc1o, g_fc1);
    cudaGetSymbolAddress((void**)&cnn1, g_cnn1);
    cudaGetSymbolAddress((void**)&cnn2, g_cnn2);
    cudaGetSymbolAddress((void**)&a1,   g_act1);
    cudaGetSymbolAddress((void**)&a2,   g_a);
    cudaGetSymbolAddress((void**)&hA,   g_h);
    cudaGetSymbolAddress((void**)&cA,   g_cst);
    cudaGetSymbolAddress((void**)&lo,   g_lstm_out);
    cudaGetSymbolAddress((void**)&o1,   g_out1);
    cudaGetSymbolAddress((void**)&mo,   g_mo);

    // --- launch order arranged so heavy convs land where ncu (-s 5 -c 1) captures ---

    // #1 conv1 (relu): pix = 94*32 = 3008, CO/8 = 4
    {
        dim3 grid((3008 + 255) / 256, 32 / 8, BB);
        conv_s2_c8<3, 5, 192, 256, 94, 126, 32, true><<<grid, 256>>>(image, conv1_w, conv1_b, c1);
    }
    // #2, #3: action path (independent of conv chain)
    { dim3 g(BB * TT / 32, 1); lin2_kernel<<<g, 256>>>(act_in, act1_w, act1_b, a1, BB * TT, 16, 2, 0); }
    { dim3 g(BB * TT / 32, 1); lin2_kernel<<<g, 256>>>(a1, act2_w, act2_b, a2, BB * TT, 16, 16, 1); }
    // #4 conv2 (relu): pix = 46*16 = 736, CO/8 = 8
    {
        dim3 grid((736 + 255) / 256, 64 / 8, BB);
        conv_s2_c8<32, 3, 94, 126, 46, 62, 64, true><<<grid, 256>>>(c1, conv2_w, conv2_b, c2);
    }
    // #5 fc1 bias init (independent)
    fc1_init_kernel<<<(BB * FC1_N + 255) / 256, 256>>>(fc1_b, fc1o);
    // #6 conv3 (no relu): pix = 22*8 = 176
    {
        dim3 grid(1, 64 / 8, BB);
        conv_s2_c8<64, 3, 46, 62, 22, 30, 64, false><<<grid, 192>>>(c2, conv3_w, conv3_b, c3);
    }
    // #7 fc1 split-K GEMM
    {
        dim3 grid(FC1_N / 64, BB / 64, 33);
        fc1_gemm_kernel<<<grid, 256>>>(c3, fc1_w, fc1o);
    }
    // fc2 / lowd chain
    { dim3 g(BB / 32, 4); lin2_kernel<<<g, 256>>>(fc1o, fc2_w, fc2_b, cnn1, BB, 128, 256, 1); }
    { dim3 g(BB / 32, 4); lin2_kernel<<<g, 256>>>(cnn1, lowd1_w, lowd1_b, cnn2, BB, 128, 128, 0); }
    { dim3 g(BB / 32, 4); lin2_kernel<<<g, 256>>>(cnn2, lowd2_w, lowd2_b, cnn1, BB, 128, 128, 1); }

    // LSTM: 15 waves
    for (int w = 0; w < LL + TT - 1; w++) {
        int l_lo = w - (TT - 1); if (l_lo < 0) l_lo = 0;
        int l_hi = w; if (l_hi > LL - 1) l_hi = LL - 1;
        int ncells = l_hi - l_lo + 1;
        lstm_wave2_kernel<<<ncells * 16, 256>>>(w, a2, cnn1, Wih0, Wih, Whh, bih, bhh, hA, cA, lo);
    }

    // heads
    { dim3 g(BB * TT / 32, 1); lin2_kernel<<<g, 256>>>(lo, out1_w, out1_b, o1, BB * TT, 32, 64, 0); }
    { dim3 g(BB * TT / 32, 1); lin2_kernel<<<g, 256>>>(o1, out2_w, out2_b, mo, BB * TT, 4, 32, 1); }

    finalize_kernel<<<(BB * TT + 255) / 256, 256>>>(mo, gt, out);
}